// round 11
// baseline (speedup 1.0000x reference)
#include <cuda_runtime.h>
#include <cstdint>

#define BB 8
#define TT 12
#define NNODE 400
#define DD 128
#define HH 8
#define HDIM 16
#define UU 16
#define CC 64
#define FFD 2048
#define MROWS (BB*TT*NNODE)   /* 38400 */
#define BTN (BB*TT)           /* 96 */

// ---- single scratch arena (no allocations allowed) ----
#define CHSZ 4915200u         /* MROWS*DD */
#define OFF_HID   (13u*CHSZ)
#define OFF_KP    (OFF_HID + (size_t)MROWS*FFD)
#define OFF_VP    (OFF_KP + (size_t)BTN*CC*DD)
#define OFF_SEN   (OFF_VP + (size_t)BTN*CC*DD)
#define OFF_ELIN  (OFF_SEN + (size_t)NNODE*DD)
#define OFF_SENX  (OFF_ELIN + (size_t)NNODE*DD)
#define OFF_T400  (OFF_SENX + (size_t)NNODE*DD)
#define OFF_XT    (OFF_T400 + (size_t)NNODE*DD)
#define OFF_B4T   (OFF_XT + (size_t)CHSZ)
#define OFF_SPET  (OFF_B4T + (size_t)CHSZ)
#define OFF_WBUF  (OFF_SPET + (size_t)NNODE*DD)
#define WBUF_WORDS 1212416u
#define SCRATCH_TOTAL (OFF_WBUF + (size_t)WBUF_WORDS)

__device__ float g_scratch[SCRATCH_TOTAL];
__device__ float g_zerobias[FFD];   // static zero-init

// WBUF word offsets
#define W_DTWQKV 0u
#define W_ATTQKV 49152u
#define W_DTWOUT 98304u
#define W_ATTOUT 114688u
#define W_SHARE  131072u
#define W_SPATIAL 147456u
#define W_FF1W1  163840u
#define W_FF1W2  425984u
#define W_FF2W1  688128u
#define W_FF2W2  950272u

// ---------------- tf32 helpers ---------------------------------------------
__device__ __forceinline__ unsigned cvt_tf32(float v) {
    unsigned r;
    asm("cvt.rna.tf32.f32 %0, %1;" : "=r"(r) : "f"(v));
    return r;
}
__device__ __forceinline__ float cvtf(float v) {
    return __uint_as_float(cvt_tf32(v));
}
__device__ __forceinline__ void mma_tf32(float& c0, float& c1, float& c2, float& c3,
                                         unsigned a0, unsigned a1, unsigned a2, unsigned a3,
                                         unsigned b0, unsigned b1) {
    asm("mma.sync.aligned.m16n8k8.row.col.f32.tf32.tf32.f32 "
        "{%0,%1,%2,%3}, {%4,%5,%6,%7}, {%8,%9}, {%0,%1,%2,%3};"
        : "+f"(c0), "+f"(c1), "+f"(c2), "+f"(c3)
        : "r"(a0), "r"(a1), "r"(a2), "r"(a3), "r"(b0), "r"(b1));
}
__device__ __forceinline__ unsigned sm_u32(const void* p) {
    return (unsigned)__cvta_generic_to_shared(p);
}
__device__ __forceinline__ void cp16(unsigned dst, const float* src, int srcsize) {
    asm volatile("cp.async.ca.shared.global [%0], [%1], 16, %2;"
                 :: "r"(dst), "l"(src), "r"(srcsize));
}
__device__ __forceinline__ void cp_commit() {
    asm volatile("cp.async.commit_group;");
}
__device__ __forceinline__ void cp_wait2() {
    asm volatile("cp.async.wait_group 2;");
}

// ---------------- prologue tf32 conversion (12 segments, one launch) -------
struct CvtSegs {
    const float* src[12];
    float* dst[12];
    int n[12];   // word counts, all multiples of 4
};
__global__ __launch_bounds__(256) void cvt_kernel(CvtSegs cs) {
    int seg = blockIdx.y;
    int n4 = cs.n[seg] >> 2;
    const float4* s = (const float4*)cs.src[seg];
    float4* d = (float4*)cs.dst[seg];
    for (int i = blockIdx.x * 256 + threadIdx.x; i < n4; i += gridDim.x * 256) {
        float4 v = s[i];
        d[i] = make_float4(cvtf(v.x), cvtf(v.y), cvtf(v.z), cvtf(v.w));
    }
}

// ---------------- tf32 GEMM core: 4-stage cp.async, 2x2 warp grid ----------
// 128x128 block, 128 threads (4 warps, 2x2), warp tile 64x64.
// A staged [m][k] stride 20, B staged [k][n] stride 136 (tf32 bits in both).
// mode: 0 = plain f32 out; 1 = relu + tf32-bit out (FFN hidden)
#define AS_WORDS (128 * 20)
#define BS_WORDS (16 * 136)
#define STAGE_WORDS (AS_WORDS + BS_WORDS)
#define NSTAGE 4
#define GEMM_SMEM (STAGE_WORDS * NSTAGE * 4) /* 75776 B */

__device__ __forceinline__ void gemm_core(
    unsigned* smem_u,
    const float* __restrict__ A, const float* __restrict__ W,
    const float* __restrict__ bias, float* __restrict__ C,
    int M, int N, int kchunk, int lda, int mode, int m0, int n0, int k0)
{
    int tid = threadIdx.x;
    int warp = tid >> 5, lane = tid & 31;
    int g = lane >> 2, tg = lane & 3;
    int wm = warp >> 1, wn = warp & 1;            // 2 x 2 warps, tile 64x64
    int nk = kchunk >> 4;

    // copy assignments (128 threads)
    int arow = tid;                                // A: 4x16B per thread (one row)
    int asz = (m0 + arow < M) ? 16 : 0;
    int brow = tid >> 3, bcol = (tid & 7) * 16;    // B: 4x16B per thread

    float acc[4][8][4];
#pragma unroll
    for (int i = 0; i < 4; i++)
#pragma unroll
        for (int j = 0; j < 8; j++)
#pragma unroll
            for (int r = 0; r < 4; r++) acc[i][j][r] = 0.f;

#define ISSUE(kt) do {                                                        \
        unsigned* Asb = smem_u + ((kt) & (NSTAGE - 1)) * STAGE_WORDS;         \
        unsigned* Bsb = Asb + AS_WORDS;                                       \
        const float* asrc = &A[(size_t)(m0 + arow) * lda + k0 + (kt) * 16];   \
        cp16(sm_u32(&Asb[arow * 20 + 0]),  asrc + 0,  asz);                   \
        cp16(sm_u32(&Asb[arow * 20 + 4]),  asrc + 4,  asz);                   \
        cp16(sm_u32(&Asb[arow * 20 + 8]),  asrc + 8,  asz);                   \
        cp16(sm_u32(&Asb[arow * 20 + 12]), asrc + 12, asz);                   \
        const float* bsrc = &W[(size_t)(k0 + (kt) * 16 + brow) * N + n0 + bcol]; \
        cp16(sm_u32(&Bsb[brow * 136 + bcol + 0]),  bsrc + 0,  16);            \
        cp16(sm_u32(&Bsb[brow * 136 + bcol + 4]),  bsrc + 4,  16);            \
        cp16(sm_u32(&Bsb[brow * 136 + bcol + 8]),  bsrc + 8,  16);            \
        cp16(sm_u32(&Bsb[brow * 136 + bcol + 12]), bsrc + 12, 16);            \
    } while (0)

#pragma unroll
    for (int s = 0; s < NSTAGE - 1; s++) {
        if (s < nk) ISSUE(s);
        cp_commit();
    }

    for (int kt = 0; kt < nk; kt++) {
        cp_wait2();
        __syncthreads();
        if (kt + NSTAGE - 1 < nk) ISSUE(kt + NSTAGE - 1);
        cp_commit();

        const unsigned* as = smem_u + (kt & (NSTAGE - 1)) * STAGE_WORDS;
        const unsigned* bs = as + AS_WORDS;

#pragma unroll
        for (int step = 0; step < 2; step++) {
            int ko = step * 8;
            unsigned af[4][4];
#pragma unroll
            for (int ma = 0; ma < 4; ma++) {
                int r = wm * 64 + ma * 16 + g;
                af[ma][0] = as[r * 20 + ko + tg];
                af[ma][1] = as[(r + 8) * 20 + ko + tg];
                af[ma][2] = as[r * 20 + ko + tg + 4];
                af[ma][3] = as[(r + 8) * 20 + ko + tg + 4];
            }
            unsigned bf[8][2];
#pragma unroll
            for (int na = 0; na < 8; na++) {
                int nc = wn * 64 + na * 8 + g;
                bf[na][0] = bs[(ko + tg) * 136 + nc];
                bf[na][1] = bs[(ko + tg + 4) * 136 + nc];
            }
#pragma unroll
            for (int ma = 0; ma < 4; ma++)
#pragma unroll
                for (int na = 0; na < 8; na++)
                    mma_tf32(acc[ma][na][0], acc[ma][na][1], acc[ma][na][2], acc[ma][na][3],
                             af[ma][0], af[ma][1], af[ma][2], af[ma][3],
                             bf[na][0], bf[na][1]);
        }
    }
#undef ISSUE

#pragma unroll
    for (int ma = 0; ma < 4; ma++) {
        int r0 = m0 + wm * 64 + ma * 16 + g;
        int r1 = r0 + 8;
#pragma unroll
        for (int na = 0; na < 8; na++) {
            int col = n0 + wn * 64 + na * 8 + tg * 2;
            float b0 = bias[col], b1 = bias[col + 1];
            float o0 = acc[ma][na][0] + b0, o1 = acc[ma][na][1] + b1;
            float o2 = acc[ma][na][2] + b0, o3 = acc[ma][na][3] + b1;
            if (mode == 1) {
                o0 = cvtf(fmaxf(o0, 0.f)); o1 = cvtf(fmaxf(o1, 0.f));
                o2 = cvtf(fmaxf(o2, 0.f)); o3 = cvtf(fmaxf(o3, 0.f));
            }
            if (r0 < M) *(float2*)&C[(size_t)r0 * N + col] = make_float2(o0, o1);
            if (r1 < M) *(float2*)&C[(size_t)r1 * N + col] = make_float2(o2, o3);
        }
    }
}

__global__ __launch_bounds__(128, 2) void gemm_tf32_kernel(
    const float* __restrict__ A, const float* __restrict__ W,
    const float* __restrict__ bias, float* __restrict__ C,
    int M, int N, int kchunk, int lda, size_t zstride, int mode)
{
    extern __shared__ unsigned smem_u[];
    const float* bp = (blockIdx.z == 0) ? bias : g_zerobias;
    gemm_core(smem_u, A, W, bp, C + (size_t)blockIdx.z * zstride,
              M, N, kchunk, lda, mode,
              blockIdx.x * 128, blockIdx.y * 128, blockIdx.z * kchunk);
}

struct MultiArgs {
    const float* W[7];
    const float* Bv[7];
    float* C[7];
};
__global__ __launch_bounds__(128, 2) void gemm_multi_kernel(
    const float* __restrict__ A, MultiArgs ma, int M)
{
    extern __shared__ unsigned smem_u[];
    int j = blockIdx.y;
    gemm_core(smem_u, A, ma.W[j], ma.Bv[j], ma.C[j],
              M, DD, DD, DD, 0, blockIdx.x * 128, 0, 0);
}

// ---------------- warp-per-row LayerNorm family ----------------------------
__device__ __forceinline__ float warp_sum(float v) {
#pragma unroll
    for (int o = 16; o; o >>= 1) v += __shfl_xor_sync(0xffffffffu, v, o);
    return v;
}

// out = tf32(LN(in))  [SEN -> GEMM input]
__global__ __launch_bounds__(256) void ln_kernel(
    const float* __restrict__ in, const float* __restrict__ g,
    const float* __restrict__ b, float* __restrict__ outp)
{
    int warp = threadIdx.x >> 5, lane = threadIdx.x & 31;
    size_t row = (size_t)blockIdx.x * 8 + warp;
    size_t i = row * 128 + lane * 4;
    float4 v = *(const float4*)&in[i];
    float mean = warp_sum(v.x + v.y + v.z + v.w) * (1.f / 128.f);
    float dx = v.x - mean, dy = v.y - mean, dz = v.z - mean, dw = v.w - mean;
    float var = warp_sum(dx*dx + dy*dy + dz*dz + dw*dw) * (1.f / 128.f);
    float rs = rsqrtf(var + 1e-5f);
    float4 gg = *(const float4*)&g[lane * 4];
    float4 bb = *(const float4*)&b[lane * 4];
    *(float4*)&outp[i] = make_float4(cvtf(dx*rs*gg.x + bb.x), cvtf(dy*rs*gg.y + bb.y),
                                     cvtf(dz*rs*gg.z + bb.z), cvtf(dw*rs*gg.w + bb.w));
}

// outp = f32 LN(x+a+b+c); outt = tf32 copy
__global__ __launch_bounds__(256) void lnsum4_kernel(
    const float* __restrict__ x, const float* __restrict__ a,
    const float* __restrict__ bp, const float* __restrict__ c,
    const float* __restrict__ g, const float* __restrict__ be,
    float* __restrict__ outp, float* __restrict__ outt)
{
    int warp = threadIdx.x >> 5, lane = threadIdx.x & 31;
    size_t row = (size_t)blockIdx.x * 8 + warp;
    size_t i = row * 128 + lane * 4;
    float4 v0 = *(const float4*)&x[i];
    float4 v1 = *(const float4*)&a[i];
    float4 v2 = *(const float4*)&bp[i];
    float4 v3 = *(const float4*)&c[i];
    float vx = v0.x + v1.x + v2.x + v3.x;
    float vy = v0.y + v1.y + v2.y + v3.y;
    float vz = v0.z + v1.z + v2.z + v3.z;
    float vw = v0.w + v1.w + v2.w + v3.w;
    float mean = warp_sum(vx + vy + vz + vw) * (1.f / 128.f);
    float dx = vx - mean, dy = vy - mean, dz = vz - mean, dw = vw - mean;
    float var = warp_sum(dx*dx + dy*dy + dz*dz + dw*dw) * (1.f / 128.f);
    float rs = rsqrtf(var + 1e-5f);
    float4 gg = *(const float4*)&g[lane * 4];
    float4 bb = *(const float4*)&be[lane * 4];
    float ox = dx*rs*gg.x + bb.x, oy = dy*rs*gg.y + bb.y;
    float oz = dz*rs*gg.z + bb.z, ow = dw*rs*gg.w + bb.w;
    *(float4*)&outp[i] = make_float4(ox, oy, oz, ow);
    *(float4*)&outt[i] = make_float4(cvtf(ox), cvtf(oy), cvtf(oz), cvtf(ow));
}

// attn2 = f32 LN(parts+s); spin = tf32(attn2 * senx)
__global__ __launch_bounds__(256) void ln2mul_kernel(
    const float* __restrict__ parts, const float* __restrict__ s,
    const float* __restrict__ senx,
    const float* __restrict__ g, const float* __restrict__ be,
    float* __restrict__ attn2, float* __restrict__ spin)
{
    int warp = threadIdx.x >> 5, lane = threadIdx.x & 31;
    size_t row = (size_t)blockIdx.x * 8 + warp;
    size_t i = row * 128 + lane * 4;
    float4 p0 = *(const float4*)&parts[i];
    float4 p1 = *(const float4*)&parts[i + (size_t)CHSZ];
    float4 p2 = *(const float4*)&parts[i + 2u * (size_t)CHSZ];
    float4 p3 = *(const float4*)&parts[i + 3u * (size_t)CHSZ];
    float4 sv = *(const float4*)&s[i];
    float vx = p0.x + p1.x + p2.x + p3.x + sv.x;
    float vy = p0.y + p1.y + p2.y + p3.y + sv.y;
    float vz = p0.z + p1.z + p2.z + p3.z + sv.z;
    float vw = p0.w + p1.w + p2.w + p3.w + sv.w;
    float mean = warp_sum(vx + vy + vz + vw) * (1.f / 128.f);
    float dx = vx - mean, dy = vy - mean, dz = vz - mean, dw = vw - mean;
    float var = warp_sum(dx*dx + dy*dy + dz*dz + dw*dw) * (1.f / 128.f);
    float rs = rsqrtf(var + 1e-5f);
    float4 gg = *(const float4*)&g[lane * 4];
    float4 bb = *(const float4*)&be[lane * 4];
    float ox = dx*rs*gg.x + bb.x, oy = dy*rs*gg.y + bb.y;
    float oz = dz*rs*gg.z + bb.z, ow = dw*rs*gg.w + bb.w;
    *(float4*)&attn2[i] = make_float4(ox, oy, oz, ow);
    float4 sx = *(const float4*)&senx[(size_t)(row % NNODE) * 128 + lane * 4];
    *(float4*)&spin[i] = make_float4(cvtf(ox*sx.x), cvtf(oy*sx.y),
                                     cvtf(oz*sx.z), cvtf(ow*sx.w));
}

__global__ __launch_bounds__(256) void final_kernel(
    const float* __restrict__ parts, const float* __restrict__ attn2,
    const float* __restrict__ g, const float* __restrict__ be,
    float* __restrict__ outp)
{
    int warp = threadIdx.x >> 5, lane = threadIdx.x & 31;
    size_t row = (size_t)blockIdx.x * 8 + warp;
    size_t i = row * 128 + lane * 4;
    float4 p0 = *(const float4*)&parts[i];
    float4 p1 = *(const float4*)&parts[i + (size_t)CHSZ];
    float4 p2 = *(const float4*)&parts[i + 2u * (size_t)CHSZ];
    float4 p3 = *(const float4*)&parts[i + 3u * (size_t)CHSZ];
    float vx = p0.x + p1.x + p2.x + p3.x;
    float vy = p0.y + p1.y + p2.y + p3.y;
    float vz = p0.z + p1.z + p2.z + p3.z;
    float vw = p0.w + p1.w + p2.w + p3.w;
    float mean = warp_sum(vx + vy + vz + vw) * (1.f / 128.f);
    float dx = vx - mean, dy = vy - mean, dz = vz - mean, dw = vw - mean;
    float var = warp_sum(dx*dx + dy*dy + dz*dz + dw*dw) * (1.f / 128.f);
    float rs = rsqrtf(var + 1e-5f);
    float4 gg = *(const float4*)&g[lane * 4];
    float4 bb = *(const float4*)&be[lane * 4];
    float4 a2 = *(const float4*)&attn2[i];
    *(float4*)&outp[i] = make_float4(a2.x + dx*rs*gg.x + bb.x, a2.y + dy*rs*gg.y + bb.y,
                                     a2.z + dz*rs*gg.z + bb.z, a2.w + dw*rs*gg.w + bb.w);
}

// ---------------- adaptive avg pool over node axis -------------------------
__global__ void pool_kernel(const float* __restrict__ Kin, const float* __restrict__ Vin,
                            float* __restrict__ Kp, float* __restrict__ Vp)
{
    int bt = blockIdx.x, c = blockIdx.y, d = threadIdx.x;
    int s = (c * NNODE) / CC;
    int e = ((c + 1) * NNODE + CC - 1) / CC;
    float inv = 1.f / (float)(e - s);
    float ak = 0.f, av = 0.f;
    for (int n = s; n < e; n++) {
        ak += Kin[((size_t)bt * NNODE + n) * DD + d];
        av += Vin[((size_t)bt * NNODE + n) * DD + d];
    }
    Kp[((size_t)bt * CC + c) * DD + d] = ak * inv;
    Vp[((size_t)bt * CC + c) * DD + d] = av * inv;
}

// ---------------- dtw attention (writes tf32 bits) -------------------------
__global__ __launch_bounds__(256) void attn_dtw_kernel(
    const float* __restrict__ Q, const float* __restrict__ K,
    const float* __restrict__ V, float* __restrict__ O)
{
    extern __shared__ float sm[];
    float* Qs = sm;               // 400*16
    float* Kt = sm + 6400;        // 16*416
    float* Vt = sm + 6400 + 6656;
    int bt = blockIdx.x, h = blockIdx.y;
    size_t base = ((size_t)bt * NNODE) * DD + h * HDIM;
    int tid = threadIdx.x;
    for (int e = tid; e < NNODE * 4; e += 256) {
        int q = e >> 2, d4 = (e & 3) << 2;
        float4 qv = *(const float4*)&Q[base + (size_t)q * DD + d4];
        float4 kv = *(const float4*)&K[base + (size_t)q * DD + d4];
        float4 vv = *(const float4*)&V[base + (size_t)q * DD + d4];
        *(float4*)&Qs[q * 16 + d4] = qv;
        Kt[(d4 + 0) * 416 + q] = kv.x; Kt[(d4 + 1) * 416 + q] = kv.y;
        Kt[(d4 + 2) * 416 + q] = kv.z; Kt[(d4 + 3) * 416 + q] = kv.w;
        Vt[(d4 + 0) * 416 + q] = vv.x; Vt[(d4 + 1) * 416 + q] = vv.y;
        Vt[(d4 + 2) * 416 + q] = vv.z; Vt[(d4 + 3) * 416 + q] = vv.w;
    }
    __syncthreads();
    int warp = tid >> 5, lane = tid & 31;
    for (int pp = warp; pp < NNODE / 2; pp += 8) {
        int qa = pp * 2;
        float qva[16], qvb[16];
#pragma unroll
        for (int d = 0; d < 16; d++) {
            qva[d] = Qs[qa * 16 + d];
            qvb[d] = Qs[qa * 16 + 16 + d];
        }
        float sa[13], sbv[13];
        float mxa = -1e30f, mxb = -1e30f;
#pragma unroll
        for (int i = 0; i < 13; i++) {
            int j = lane + (i << 5);
            float s0 = -1e30f, s1 = -1e30f;
            if (j < NNODE) {
                s0 = 0.f; s1 = 0.f;
#pragma unroll
                for (int d = 0; d < 16; d++) {
                    float kv = Kt[d * 416 + j];
                    s0 = fmaf(qva[d], kv, s0);
                    s1 = fmaf(qvb[d], kv, s1);
                }
                s0 *= 0.25f; s1 *= 0.25f;
            }
            sa[i] = s0; sbv[i] = s1;
            mxa = fmaxf(mxa, s0); mxb = fmaxf(mxb, s1);
        }
#pragma unroll
        for (int o = 16; o; o >>= 1) {
            mxa = fmaxf(mxa, __shfl_xor_sync(0xffffffffu, mxa, o));
            mxb = fmaxf(mxb, __shfl_xor_sync(0xffffffffu, mxb, o));
        }
        float la = 0.f, lb = 0.f;
#pragma unroll
        for (int i = 0; i < 13; i++) {
            int j = lane + (i << 5);
            float pa = (j < NNODE) ? __expf(sa[i] - mxa) : 0.f;
            float pb = (j < NNODE) ? __expf(sbv[i] - mxb) : 0.f;
            sa[i] = pa; sbv[i] = pb;
            la += pa; lb += pb;
        }
#pragma unroll
        for (int o = 16; o; o >>= 1) {
            la += __shfl_xor_sync(0xffffffffu, la, o);
            lb += __shfl_xor_sync(0xffffffffu, lb, o);
        }
        float acca[16], accb[16];
#pragma unroll
        for (int d = 0; d < 16; d++) { acca[d] = 0.f; accb[d] = 0.f; }
#pragma unroll
        for (int i = 0; i < 13; i++) {
            int j = lane + (i << 5);
            if (j < NNODE) {
                float pa = sa[i], pb = sbv[i];
#pragma unroll
                for (int d = 0; d < 16; d++) {
                    float vv = Vt[d * 416 + j];
                    acca[d] = fmaf(pa, vv, acca[d]);
                    accb[d] = fmaf(pb, vv, accb[d]);
                }
            }
        }
#pragma unroll
        for (int d = 0; d < 16; d++) {
#pragma unroll
            for (int o = 16; o; o >>= 1) {
                acca[d] += __shfl_xor_sync(0xffffffffu, acca[d], o);
                accb[d] += __shfl_xor_sync(0xffffffffu, accb[d], o);
            }
        }
        if (lane < 16) {
            O[base + (size_t)qa * DD + lane]       = cvtf(acca[lane] / la);
            O[base + (size_t)(qa + 1) * DD + lane] = cvtf(accb[lane] / lb);
        }
    }
}

// ---------------- pooled attention (writes tf32 bits) ----------------------
__global__ __launch_bounds__(256) void attn_adp_kernel(
    const float* __restrict__ Q, const float* __restrict__ Kp,
    const float* __restrict__ Vp, const float* __restrict__ pos,
    float* __restrict__ O)
{
    __shared__ float Qs[NNODE * 16];
    __shared__ float Kt[16 * 64];
    __shared__ float Vt[16 * 64];
    int bt = blockIdx.x, h = blockIdx.y, tid = threadIdx.x;
    size_t qbase = ((size_t)bt * NNODE) * DD + h * HDIM;
    size_t kbase = ((size_t)bt * CC) * DD + h * HDIM;
    for (int e = tid; e < NNODE * 4; e += 256) {
        int q = e >> 2, d4 = (e & 3) << 2;
        *(float4*)&Qs[q * 16 + d4] = *(const float4*)&Q[qbase + (size_t)q * DD + d4];
    }
    {
        int c = tid >> 2, d4 = (tid & 3) << 2;
        float4 kv = *(const float4*)&Kp[kbase + (size_t)c * DD + d4];
        float4 vv = *(const float4*)&Vp[kbase + (size_t)c * DD + d4];
        Kt[(d4 + 0) * 64 + c] = kv.x; Kt[(d4 + 1) * 64 + c] = kv.y;
        Kt[(d4 + 2) * 64 + c] = kv.z; Kt[(d4 + 3) * 64 + c] = kv.w;
        Vt[(d4 + 0) * 64 + c] = vv.x; Vt[(d4 + 1) * 64 + c] = vv.y;
        Vt[(d4 + 2) * 64 + c] = vv.z; Vt[(d4 + 3) * 64 + c] = vv.w;
    }
    __syncthreads();
    int warp = tid >> 5, lane = tid & 31;
    for (int pp = warp; pp < NNODE / 2; pp += 8) {
        int qa = pp * 2;
        float qva[16], qvb[16];
#pragma unroll
        for (int d = 0; d < 16; d++) {
            qva[d] = Qs[qa * 16 + d];
            qvb[d] = Qs[qa * 16 + 16 + d];
        }
        float s00 = 0.f, s01 = 0.f, s10 = 0.f, s11 = 0.f;
#pragma unroll
        for (int d = 0; d < 16; d++) {
            float k0 = Kt[d * 64 + lane], k1 = Kt[d * 64 + lane + 32];
            s00 = fmaf(qva[d], k0, s00); s01 = fmaf(qva[d], k1, s01);
            s10 = fmaf(qvb[d], k0, s10); s11 = fmaf(qvb[d], k1, s11);
        }
        s00 = s00 * 0.25f + pos[(size_t)qa * 64 + lane];
        s01 = s01 * 0.25f + pos[(size_t)qa * 64 + lane + 32];
        s10 = s10 * 0.25f + pos[(size_t)(qa + 1) * 64 + lane];
        s11 = s11 * 0.25f + pos[(size_t)(qa + 1) * 64 + lane + 32];
        float mxa = fmaxf(s00, s01), mxb = fmaxf(s10, s11);
#pragma unroll
        for (int o = 16; o; o >>= 1) {
            mxa = fmaxf(mxa, __shfl_xor_sync(0xffffffffu, mxa, o));
            mxb = fmaxf(mxb, __shfl_xor_sync(0xffffffffu, mxb, o));
        }
        float p00 = __expf(s00 - mxa), p01 = __expf(s01 - mxa);
        float p10 = __expf(s10 - mxb), p11 = __expf(s11 - mxb);
        float la = p00 + p01, lb = p10 + p11;
#pragma unroll
        for (int o = 16; o; o >>= 1) {
            la += __shfl_xor_sync(0xffffffffu, la, o);
            lb += __shfl_xor_sync(0xffffffffu, lb, o);
        }
        float acca[16], accb[16];
#pragma unroll
        for (int d = 0; d < 16; d++) {
            float v0 = Vt[d * 64 + lane], v1 = Vt[d * 64 + lane + 32];
            acca[d] = p00 * v0 + p01 * v1;
            accb[d] = p10 * v0 + p11 * v1;
        }
#pragma unroll
        for (int d = 0; d < 16; d++) {
#pragma unroll
            for (int o = 16; o; o >>= 1) {
                acca[d] += __shfl_xor_sync(0xffffffffu, acca[d], o);
                accb[d] += __shfl_xor_sync(0xffffffffu, accb[d], o);
            }
        }
        if (lane < 16) {
            O[qbase + (size_t)qa * DD + lane]       = cvtf(acca[lane] / la);
            O[qbase + (size_t)(qa + 1) * DD + lane] = cvtf(accb[lane] / lb);
        }
    }
}

// ---------------- GEANet edge path (sen -> sen_extra) ----------------------
__global__ void edge_kernel(const float* __restrict__ elin, const float* __restrict__ ew,
                            const float* __restrict__ eb, float* __restrict__ senx,
                            float* __restrict__ outtail)
{
    __shared__ float s0[128], s1[128], s2[128];
    int n = blockIdx.x, t = threadIdx.x;
    int h = t >> 4, u = t & 15;
    s0[t] = elin[(size_t)n * 128 + t];
    __syncthreads();
    float acc = eb[u];
#pragma unroll
    for (int k = 0; k < 16; k++) acc = fmaf(s0[k * 8 + h], ew[k * 16 + u], acc);
    s1[t] = acc;
    __syncthreads();
    float mx = -1e30f;
#pragma unroll
    for (int hh = 0; hh < 8; hh++) mx = fmaxf(mx, s1[hh * 16 + u]);
    float sume = 0.f;
#pragma unroll
    for (int hh = 0; hh < 8; hh++) sume += __expf(s1[hh * 16 + u] - mx);
    float a = __expf(acc - mx) / sume;
    s2[t] = a;
    __syncthreads();
    float rs = 0.f;
#pragma unroll
    for (int uu = 0; uu < 16; uu++) rs += s2[h * 16 + uu];
    float a2 = a / rs;
    __syncthreads();
    s0[t] = a2;
    __syncthreads();
    float y = eb[16 + u];
#pragma unroll
    for (int k = 0; k < 16; k++) y = fmaf(s0[h * 16 + k], ew[256 + k * 16 + u], y);
    senx[(size_t)n * 128 + t] = y;
    outtail[(size_t)n * 128 + t] = y;
}

// ---------------- GEANet node path (reshape-of-transpose perm) -------------
__global__ void node_kernel(const float* __restrict__ share, const float* __restrict__ nw,
                            const float* __restrict__ nb, float* __restrict__ extra)
{
    __shared__ float s0[128], s1[128], s2[128];
    int row = blockIdx.x;
    int b = row / (TT * NNODE), p = row % (TT * NNODE);
    int nn = p / TT, ll = p % TT;
    int t = threadIdx.x;
    int h = t >> 4, u = t & 15;
    s0[t] = share[(((size_t)b * TT + ll) * NNODE + nn) * 128 + t];
    __syncthreads();
    float acc = nb[u];
#pragma unroll
    for (int k = 0; k < 16; k++) acc = fmaf(s0[h * 16 + k], nw[k * 16 + u], acc);
    s1[t] = acc;
    __syncthreads();
    float mx = -1e30f;
#pragma unroll
    for (int hh = 0; hh < 8; hh++) mx = fmaxf(mx, s1[hh * 16 + u]);
    float sume = 0.f;
#pragma unroll
    for (int hh = 0; hh < 8; hh++) sume += __expf(s1[hh * 16 + u] - mx);
    float a = __expf(acc - mx) / sume;
    s2[t] = a;
    __syncthreads();
    float rs = 0.f;
#pragma unroll
    for (int uu = 0; uu < 16; uu++) rs += s2[h * 16 + uu];
    float a2 = a / rs;
    __syncthreads();
    s0[t] = a2;
    __syncthreads();
    float y = nb[16 + u];
#pragma unroll
    for (int k = 0; k < 16; k++) y = fmaf(s0[h * 16 + k], nw[256 + k * 16 + u], y);
    extra[(size_t)row * 128 + t] = y;
}

// ---------------- host orchestration ---------------------------------------
extern "C" void kernel_launch(void* const* d_in, const int* in_sizes, int n_in,
                              void* d_out, int out_size)
{
    const float* x         = (const float*)d_in[0];
    const float* spe       = (const float*)d_in[1];
    const float* dtw_qkv_w = (const float*)d_in[2];
    const float* dtw_qkv_b = (const float*)d_in[3];
    const float* dtw_out_w = (const float*)d_in[4];
    const float* dtw_out_b = (const float*)d_in[5];
    const float* att_qkv_w = (const float*)d_in[6];
    const float* att_qkv_b = (const float*)d_in[7];
    const float* att_out_w = (const float*)d_in[8];
    const float* att_out_b = (const float*)d_in[9];
    const float* adp_pos   = (const float*)d_in[10];
    const float* share_w   = (const float*)d_in[11];
    const float* share_b   = (const float*)d_in[12];
    const float* node_w    = (const float*)d_in[13];
    const float* node_b    = (const float*)d_in[14];
    const float* edge_w    = (const float*)d_in[15];
    const float* edge_b    = (const float*)d_in[16];
    const float* spatial_w = (const float*)d_in[17];
    const float* spatial_b = (const float*)d_in[18];
    const float* ff1w1     = (const float*)d_in[19];
    const float* ff1b1     = (const float*)d_in[20];
    const float* ff1w2     = (const float*)d_in[21];
    const float* ff1b2     = (const float*)d_in[22];
    const float* ff2w1     = (const float*)d_in[23];
    const float* ff2b1     = (const float*)d_in[24];
    const float* ff2w2     = (const float*)d_in[25];
    const float* ff2b2     = (const float*)d_in[26];
    const float* lns       = (const float*)d_in[27];
    const float* lnb       = (const float*)d_in[28];
    float* out = (float*)d_out;

    float* g = nullptr;
    { void* p; cudaGetSymbolAddress(&p, g_scratch); g = (float*)p; }
    float* PART = g + 0u * CHSZ;
    float* Q1   = g + 0u * CHSZ;
    float* K1   = g + 1u * CHSZ;
    float* V1   = g + 2u * CHSZ;
    float* Q2   = g + 3u * CHSZ;
    float* K2   = g + 4u * CHSZ;
    float* V2   = g + 5u * CHSZ;
    float* SHR  = g + 6u * CHSZ;
    float* DTW  = g + 7u * CHSZ;
    float* OA   = g + 8u * CHSZ;
    float* B1   = g + 9u * CHSZ;
    float* B2   = g + 10u * CHSZ;
    float* B3   = g + 11u * CHSZ;
    float* B4   = g + 12u * CHSZ;
    float* HID  = g + OFF_HID;
    float* KP   = g + OFF_KP;
    float* VP   = g + OFF_VP;
    float* SEN  = g + OFF_SEN;
    float* ELIN = g + OFF_ELIN;
    float* SENX = g + OFF_SENX;
    float* T400 = g + OFF_T400;
    float* XT   = g + OFF_XT;
    float* B4T  = g + OFF_B4T;
    float* SPET = g + OFF_SPET;
    float* WB   = g + OFF_WBUF;

    cudaFuncSetAttribute(attn_dtw_kernel,
                         cudaFuncAttributeMaxDynamicSharedMemorySize, 78848);
    cudaFuncSetAttribute(gemm_tf32_kernel,
                         cudaFuncAttributeMaxDynamicSharedMemorySize, GEMM_SMEM);
    cudaFuncSetAttribute(gemm_multi_kernel,
                         cudaFuncAttributeMaxDynamicSharedMemorySize, GEMM_SMEM);

    // prologue: convert x, spe, all GEMM weights to tf32
    {
        CvtSegs cs;
        cs.src[0] = x;         cs.dst[0] = XT;                cs.n[0] = MROWS * DD;
        cs.src[1] = spe;       cs.dst[1] = SPET;              cs.n[1] = NNODE * DD;
        cs.src[2] = dtw_qkv_w; cs.dst[2] = WB + W_DTWQKV;     cs.n[2] = 3 * DD * DD;
        cs.src[3] = att_qkv_w; cs.dst[3] = WB + W_ATTQKV;     cs.n[3] = 3 * DD * DD;
        cs.src[4] = dtw_out_w; cs.dst[4] = WB + W_DTWOUT;     cs.n[4] = DD * DD;
        cs.src[5] = att_out_w; cs.dst[5] = WB + W_ATTOUT;     cs.n[5] = DD * DD;
        cs.src[6] = share_w;   cs.dst[6] = WB + W_SHARE;      cs.n[6] = DD * DD;
        cs.src[7] = spatial_w; cs.dst[7] = WB + W_SPATIAL;    cs.n[7] = DD * DD;
        cs.src[8] = ff1w1;     cs.dst[8] = WB + W_FF1W1;      cs.n[8] = DD * FFD;
        cs.src[9] = ff1w2;     cs.dst[9] = WB + W_FF1W2;      cs.n[9] = FFD * DD;
        cs.src[10] = ff2w1;    cs.dst[10] = WB + W_FF2W1;     cs.n[10] = DD * FFD;
        cs.src[11] = ff2w2;    cs.dst[11] = WB + W_FF2W2;     cs.n[11] = FFD * DD;
        cvt_kernel<<<dim3(128, 12), 256>>>(cs);
    }

#define GEMM(A_, W_, Bi_, C_, M_, N_, K_, LDA_, MO_) \
    gemm_tf32_kernel<<<dim3(((M_) + 127) / 128, (N_) / 128, 1), 128, GEMM_SMEM>>>( \
        A_, W_, Bi_, C_, M_, N_, K_, LDA_, 0, MO_)

    // fused QKV projections + GEANet share (one launch)
    {
        MultiArgs ma;
        ma.W[0] = WB + W_DTWQKV + 0 * DD * DD; ma.Bv[0] = dtw_qkv_b + 0 * DD; ma.C[0] = Q1;
        ma.W[1] = WB + W_DTWQKV + 1 * DD * DD; ma.Bv[1] = dtw_qkv_b + 1 * DD; ma.C[1] = K1;
        ma.W[2] = WB + W_DTWQKV + 2 * DD * DD; ma.Bv[2] = dtw_qkv_b + 2 * DD; ma.C[2] = V1;
        ma.W[3] = WB + W_ATTQKV + 0 * DD * DD; ma.Bv[3] = att_qkv_b + 0 * DD; ma.C[3] = Q2;
        ma.W[4] = WB + W_ATTQKV + 1 * DD * DD; ma.Bv[4] = att_qkv_b + 1 * DD; ma.C[4] = K2;
        ma.W[5] = WB + W_ATTQKV + 2 * DD * DD; ma.Bv[5] = att_qkv_b + 2 * DD; ma.C[5] = V2;
        ma.W[6] = WB + W_SHARE;                ma.Bv[6] = share_b;            ma.C[6] = SHR;
        gemm_multi_kernel<<<dim3(MROWS / 128, 7), 128, GEMM_SMEM>>>(XT, ma, MROWS);
    }

    // sen path
    GEMM(SPET, WB + W_SPATIAL, spatial_b, T400, NNODE, DD, DD, DD, 0);
    ln_kernel<<<NNODE / 8, 256>>>(T400, lns + 3 * 128, lnb + 3 * 128, SEN);  // tf32 out
    GEMM(SEN, WB + W_SHARE, share_b, ELIN, NNODE, DD, DD, DD, 0);
    edge_kernel<<<NNODE, 128>>>(ELIN, edge_w, edge_b, SENX, out + (size_t)MROWS * DD);

    // GEANet node path
    node_kernel<<<MROWS, 128>>>(SHR, node_w, node_b, B1);

    // dtw attention (tf32 out) + out projection
    attn_dtw_kernel<<<dim3(BTN, HH), 256, 78848>>>(Q1, K1, V1, B2);
    GEMM(B2, WB + W_DTWOUT, dtw_out_b, DTW, MROWS, DD, DD, DD, 0);

    // pooled attention (tf32 out) + out projection
    pool_kernel<<<dim3(BTN, CC), 128>>>(K2, V2, KP, VP);
    attn_adp_kernel<<<dim3(BTN, HH), 256>>>(Q2, KP, VP, adp_pos, B2);
    GEMM(B2, WB + W_ATTOUT, att_out_b, OA, MROWS, DD, DD, DD, 0);

    // ln1: f32 B4 (residual) + tf32 B4T (GEMM input)
    lnsum4_kernel<<<MROWS / 8, 256>>>(x, OA, DTW, B1, lns + 0, lnb + 0, B4, B4T);

    // feed_forward1: up (relu, tf32 out) + split-K=4 down; ln2 + senx mul
    GEMM(B4T, WB + W_FF1W1, ff1b1, HID, MROWS, FFD, DD, DD, 1);
    gemm_tf32_kernel<<<dim3(MROWS / 128, 1, 4), 128, GEMM_SMEM>>>(
        HID, WB + W_FF1W2, ff1b2, PART, MROWS, DD, FFD / 4, FFD, (size_t)CHSZ, 0);
    ln2mul_kernel<<<MROWS / 8, 256>>>(PART, B4, SENX, lns + 128, lnb + 128, B2, B3);

    // feed_forward2: up (relu, tf32 out) + split-K=4 down; final LN + residual
    GEMM(B3, WB + W_FF2W1, ff2b1, HID, MROWS, FFD, DD, DD, 1);
    gemm_tf32_kernel<<<dim3(MROWS / 128, 1, 4), 128, GEMM_SMEM>>>(
        HID, WB + W_FF2W2, ff2b2, PART, MROWS, DD, FFD / 4, FFD, (size_t)CHSZ, 0);
    final_kernel<<<MROWS / 8, 256>>>(PART, B2, lns + 2 * 128, lnb + 2 * 128, out);
#undef GEMM
}

// round 12
// speedup vs baseline: 1.1226x; 1.1226x over previous
#include <cuda_runtime.h>
#include <cstdint>

#define BB 8
#define TT 12
#define NNODE 400
#define DD 128
#define HH 8
#define HDIM 16
#define UU 16
#define CC 64
#define FFD 2048
#define MROWS (BB*TT*NNODE)   /* 38400 */
#define BTN (BB*TT)           /* 96 */

// ---- single scratch arena (no allocations allowed) ----
#define CHSZ 4915200u         /* MROWS*DD */
#define OFF_HID   (13u*CHSZ)
#define OFF_KP    (OFF_HID + (size_t)MROWS*FFD)
#define OFF_VP    (OFF_KP + (size_t)BTN*CC*DD)
#define OFF_SEN   (OFF_VP + (size_t)BTN*CC*DD)
#define OFF_ELIN  (OFF_SEN + (size_t)NNODE*DD)
#define OFF_SENX  (OFF_ELIN + (size_t)NNODE*DD)
#define OFF_T400  (OFF_SENX + (size_t)NNODE*DD)
#define SCRATCH_TOTAL (OFF_T400 + (size_t)NNODE*DD)

__device__ float g_scratch[SCRATCH_TOTAL];
__device__ float g_zerobias[FFD];   // static zero-init

// ---------------- tf32 helpers ---------------------------------------------
__device__ __forceinline__ unsigned cvt_tf32(float v) {
    unsigned r;
    asm("cvt.rna.tf32.f32 %0, %1;" : "=r"(r) : "f"(v));
    return r;
}
__device__ __forceinline__ void mma_tf32(float& c0, float& c1, float& c2, float& c3,
                                         unsigned a0, unsigned a1, unsigned a2, unsigned a3,
                                         unsigned b0, unsigned b1) {
    asm("mma.sync.aligned.m16n8k8.row.col.f32.tf32.tf32.f32 "
        "{%0,%1,%2,%3}, {%4,%5,%6,%7}, {%8,%9}, {%0,%1,%2,%3};"
        : "+f"(c0), "+f"(c1), "+f"(c2), "+f"(c3)
        : "r"(a0), "r"(a1), "r"(a2), "r"(a3), "r"(b0), "r"(b1));
}
__device__ __forceinline__ unsigned sm_u32(const void* p) {
    return (unsigned)__cvta_generic_to_shared(p);
}
__device__ __forceinline__ void cp16(unsigned dst, const float* src, int srcsize) {
    asm volatile("cp.async.ca.shared.global [%0], [%1], 16, %2;"
                 :: "r"(dst), "l"(src), "r"(srcsize));
}
__device__ __forceinline__ void cp_commit() {
    asm volatile("cp.async.commit_group;");
}
__device__ __forceinline__ void cp_wait1() {
    asm volatile("cp.async.wait_group 1;");
}

// ---------------- tf32 GEMM core (R8 known-best: 3-stage cp.async) ---------
// 128x128 block, 256 threads, 8 warps (2x4), warp tile 64x32.
// A staged [m][k] stride 20 (raw f32), B staged [k][n] stride 136 (raw f32).
// cvt.rna applied on fragment registers after LDS (tf32-rna numerics).
#define AS_WORDS (128 * 20)                 /* 10240 B */
#define BS_WORDS (16 * 136)                 /*  8704 B */
#define STAGE_WORDS (AS_WORDS + BS_WORDS)   /* 18944 B */
#define NSTAGE 3
#define GEMM_SMEM (STAGE_WORDS * NSTAGE * 4) /* 56832 B */

__device__ __forceinline__ void gemm_core(
    unsigned* smem_u,
    const float* __restrict__ A, const float* __restrict__ W,
    const float* __restrict__ bias, float* __restrict__ C,
    int M, int N, int kchunk, int lda, int relu, int m0, int n0, int k0)
{
    int tid = threadIdx.x;
    int warp = tid >> 5, lane = tid & 31;
    int g = lane >> 2, tg = lane & 3;
    int wm = warp >> 2, wn = warp & 3;            // 2 x 4
    int nk = kchunk >> 4;

    int arow = tid >> 1, akoff = (tid & 1) * 8;   // A: 2x16B per thread
    int asz = (m0 + arow < M) ? 16 : 0;
    int bc0 = tid * 2;                            // B: 2x16B per thread
    int br0 = bc0 >> 5, bn0 = (bc0 & 31) * 4;
    int br1 = (bc0 + 1) >> 5, bn1 = ((bc0 + 1) & 31) * 4;

    float acc[4][4][4];
#pragma unroll
    for (int i = 0; i < 4; i++)
#pragma unroll
        for (int j = 0; j < 4; j++)
#pragma unroll
            for (int r = 0; r < 4; r++) acc[i][j][r] = 0.f;

#define ISSUE(kt) do {                                                        \
        unsigned* Asb = smem_u + ((kt) % NSTAGE) * STAGE_WORDS;               \
        unsigned* Bsb = Asb + AS_WORDS;                                       \
        const float* asrc = &A[(size_t)(m0 + arow) * lda + k0 + (kt) * 16 + akoff]; \
        cp16(sm_u32(&Asb[arow * 20 + akoff]),     asrc,     asz);             \
        cp16(sm_u32(&Asb[arow * 20 + akoff + 4]), asrc + 4, asz);             \
        cp16(sm_u32(&Bsb[br0 * 136 + bn0]),                                   \
             &W[(size_t)(k0 + (kt) * 16 + br0) * N + n0 + bn0], 16);          \
        cp16(sm_u32(&Bsb[br1 * 136 + bn1]),                                   \
             &W[(size_t)(k0 + (kt) * 16 + br1) * N + n0 + bn1], 16);          \
    } while (0)

    // prologue: stages 0..NSTAGE-2
#pragma unroll
    for (int s = 0; s < NSTAGE - 1; s++) {
        if (s < nk) ISSUE(s);
        cp_commit();
    }

    for (int kt = 0; kt < nk; kt++) {
        if (kt + NSTAGE - 1 < nk) ISSUE(kt + NSTAGE - 1);
        cp_commit();
        cp_wait1();
        __syncthreads();

        const unsigned* as = smem_u + (kt % NSTAGE) * STAGE_WORDS;
        const unsigned* bs = as + AS_WORDS;

#pragma unroll
        for (int step = 0; step < 2; step++) {
            int ko = step * 8;
            unsigned af[4][4];
#pragma unroll
            for (int ma = 0; ma < 4; ma++) {
                int r = wm * 64 + ma * 16 + g;
                af[ma][0] = cvt_tf32(__uint_as_float(as[r * 20 + ko + tg]));
                af[ma][1] = cvt_tf32(__uint_as_float(as[(r + 8) * 20 + ko + tg]));
                af[ma][2] = cvt_tf32(__uint_as_float(as[r * 20 + ko + tg + 4]));
                af[ma][3] = cvt_tf32(__uint_as_float(as[(r + 8) * 20 + ko + tg + 4]));
            }
            unsigned bf[4][2];
#pragma unroll
            for (int na = 0; na < 4; na++) {
                int nc = wn * 32 + na * 8 + g;
                bf[na][0] = cvt_tf32(__uint_as_float(bs[(ko + tg) * 136 + nc]));
                bf[na][1] = cvt_tf32(__uint_as_float(bs[(ko + tg + 4) * 136 + nc]));
            }
#pragma unroll
            for (int ma = 0; ma < 4; ma++)
#pragma unroll
                for (int na = 0; na < 4; na++)
                    mma_tf32(acc[ma][na][0], acc[ma][na][1], acc[ma][na][2], acc[ma][na][3],
                             af[ma][0], af[ma][1], af[ma][2], af[ma][3],
                             bf[na][0], bf[na][1]);
        }
        __syncthreads();
    }
#undef ISSUE

#pragma unroll
    for (int ma = 0; ma < 4; ma++) {
        int r0 = m0 + wm * 64 + ma * 16 + g;
        int r1 = r0 + 8;
#pragma unroll
        for (int na = 0; na < 4; na++) {
            int col = n0 + wn * 32 + na * 8 + tg * 2;
            float b0 = bias[col], b1 = bias[col + 1];
            float o0 = acc[ma][na][0] + b0, o1 = acc[ma][na][1] + b1;
            float o2 = acc[ma][na][2] + b0, o3 = acc[ma][na][3] + b1;
            if (relu) {
                o0 = fmaxf(o0, 0.f); o1 = fmaxf(o1, 0.f);
                o2 = fmaxf(o2, 0.f); o3 = fmaxf(o3, 0.f);
            }
            if (r0 < M) *(float2*)&C[(size_t)r0 * N + col] = make_float2(o0, o1);
            if (r1 < M) *(float2*)&C[(size_t)r1 * N + col] = make_float2(o2, o3);
        }
    }
}

// generic wrapper (split-K via blockIdx.z)
__global__ __launch_bounds__(256, 2) void gemm_tf32_kernel(
    const float* __restrict__ A, const float* __restrict__ W,
    const float* __restrict__ bias, float* __restrict__ C,
    int M, int N, int kchunk, int lda, size_t zstride, int relu)
{
    extern __shared__ unsigned smem_u[];
    const float* bp = (blockIdx.z == 0) ? bias : g_zerobias;
    gemm_core(smem_u, A, W, bp, C + (size_t)blockIdx.z * zstride,
              M, N, kchunk, lda, relu,
              blockIdx.x * 128, blockIdx.y * 128, blockIdx.z * kchunk);
}

// fused 7-way projection wrapper: all read A, N=K=lda=128
struct MultiArgs {
    const float* W[7];
    const float* Bv[7];
    float* C[7];
};
__global__ __launch_bounds__(256, 2) void gemm_multi_kernel(
    const float* __restrict__ A, MultiArgs ma, int M)
{
    extern __shared__ unsigned smem_u[];
    int j = blockIdx.y;
    gemm_core(smem_u, A, ma.W[j], ma.Bv[j], ma.C[j],
              M, DD, DD, DD, 0, blockIdx.x * 128, 0, 0);
}

// ---------------- warp-per-row LayerNorm family ----------------------------
__device__ __forceinline__ float warp_sum(float v) {
#pragma unroll
    for (int o = 16; o; o >>= 1) v += __shfl_xor_sync(0xffffffffu, v, o);
    return v;
}

__global__ __launch_bounds__(256) void ln_kernel(
    const float* __restrict__ in, const float* __restrict__ g,
    const float* __restrict__ b, float* __restrict__ outp)
{
    int warp = threadIdx.x >> 5, lane = threadIdx.x & 31;
    size_t row = (size_t)blockIdx.x * 8 + warp;
    size_t i = row * 128 + lane * 4;
    float4 v = *(const float4*)&in[i];
    float mean = warp_sum(v.x + v.y + v.z + v.w) * (1.f / 128.f);
    float dx = v.x - mean, dy = v.y - mean, dz = v.z - mean, dw = v.w - mean;
    float var = warp_sum(dx*dx + dy*dy + dz*dz + dw*dw) * (1.f / 128.f);
    float rs = rsqrtf(var + 1e-5f);
    float4 gg = *(const float4*)&g[lane * 4];
    float4 bb = *(const float4*)&b[lane * 4];
    *(float4*)&outp[i] = make_float4(dx*rs*gg.x + bb.x, dy*rs*gg.y + bb.y,
                                     dz*rs*gg.z + bb.z, dw*rs*gg.w + bb.w);
}

__global__ __launch_bounds__(256) void lnsum4_kernel(
    const float* __restrict__ x, const float* __restrict__ a,
    const float* __restrict__ bp, const float* __restrict__ c,
    const float* __restrict__ g, const float* __restrict__ be,
    float* __restrict__ outp)
{
    int warp = threadIdx.x >> 5, lane = threadIdx.x & 31;
    size_t row = (size_t)blockIdx.x * 8 + warp;
    size_t i = row * 128 + lane * 4;
    float4 v0 = *(const float4*)&x[i];
    float4 v1 = *(const float4*)&a[i];
    float4 v2 = *(const float4*)&bp[i];
    float4 v3 = *(const float4*)&c[i];
    float vx = v0.x + v1.x + v2.x + v3.x;
    float vy = v0.y + v1.y + v2.y + v3.y;
    float vz = v0.z + v1.z + v2.z + v3.z;
    float vw = v0.w + v1.w + v2.w + v3.w;
    float mean = warp_sum(vx + vy + vz + vw) * (1.f / 128.f);
    float dx = vx - mean, dy = vy - mean, dz = vz - mean, dw = vw - mean;
    float var = warp_sum(dx*dx + dy*dy + dz*dz + dw*dw) * (1.f / 128.f);
    float rs = rsqrtf(var + 1e-5f);
    float4 gg = *(const float4*)&g[lane * 4];
    float4 bb = *(const float4*)&be[lane * 4];
    *(float4*)&outp[i] = make_float4(dx*rs*gg.x + bb.x, dy*rs*gg.y + bb.y,
                                     dz*rs*gg.z + bb.z, dw*rs*gg.w + bb.w);
}

__global__ __launch_bounds__(256) void ln2mul_kernel(
    const float* __restrict__ parts, const float* __restrict__ s,
    const float* __restrict__ senx,
    const float* __restrict__ g, const float* __restrict__ be,
    float* __restrict__ attn2, float* __restrict__ spin)
{
    int warp = threadIdx.x >> 5, lane = threadIdx.x & 31;
    size_t row = (size_t)blockIdx.x * 8 + warp;
    size_t i = row * 128 + lane * 4;
    float4 p0 = *(const float4*)&parts[i];
    float4 p1 = *(const float4*)&parts[i + (size_t)CHSZ];
    float4 p2 = *(const float4*)&parts[i + 2u * (size_t)CHSZ];
    float4 p3 = *(const float4*)&parts[i + 3u * (size_t)CHSZ];
    float4 sv = *(const float4*)&s[i];
    float vx = p0.x + p1.x + p2.x + p3.x + sv.x;
    float vy = p0.y + p1.y + p2.y + p3.y + sv.y;
    float vz = p0.z + p1.z + p2.z + p3.z + sv.z;
    float vw = p0.w + p1.w + p2.w + p3.w + sv.w;
    float mean = warp_sum(vx + vy + vz + vw) * (1.f / 128.f);
    float dx = vx - mean, dy = vy - mean, dz = vz - mean, dw = vw - mean;
    float var = warp_sum(dx*dx + dy*dy + dz*dz + dw*dw) * (1.f / 128.f);
    float rs = rsqrtf(var + 1e-5f);
    float4 gg = *(const float4*)&g[lane * 4];
    float4 bb = *(const float4*)&be[lane * 4];
    float ox = dx*rs*gg.x + bb.x, oy = dy*rs*gg.y + bb.y;
    float oz = dz*rs*gg.z + bb.z, ow = dw*rs*gg.w + bb.w;
    *(float4*)&attn2[i] = make_float4(ox, oy, oz, ow);
    float4 sx = *(const float4*)&senx[(size_t)(row % NNODE) * 128 + lane * 4];
    *(float4*)&spin[i] = make_float4(ox*sx.x, oy*sx.y, oz*sx.z, ow*sx.w);
}

__global__ __launch_bounds__(256) void final_kernel(
    const float* __restrict__ parts, const float* __restrict__ attn2,
    const float* __restrict__ g, const float* __restrict__ be,
    float* __restrict__ outp)
{
    int warp = threadIdx.x >> 5, lane = threadIdx.x & 31;
    size_t row = (size_t)blockIdx.x * 8 + warp;
    size_t i = row * 128 + lane * 4;
    float4 p0 = *(const float4*)&parts[i];
    float4 p1 = *(const float4*)&parts[i + (size_t)CHSZ];
    float4 p2 = *(const float4*)&parts[i + 2u * (size_t)CHSZ];
    float4 p3 = *(const float4*)&parts[i + 3u * (size_t)CHSZ];
    float vx = p0.x + p1.x + p2.x + p3.x;
    float vy = p0.y + p1.y + p2.y + p3.y;
    float vz = p0.z + p1.z + p2.z + p3.z;
    float vw = p0.w + p1.w + p2.w + p3.w;
    float mean = warp_sum(vx + vy + vz + vw) * (1.f / 128.f);
    float dx = vx - mean, dy = vy - mean, dz = vz - mean, dw = vw - mean;
    float var = warp_sum(dx*dx + dy*dy + dz*dz + dw*dw) * (1.f / 128.f);
    float rs = rsqrtf(var + 1e-5f);
    float4 gg = *(const float4*)&g[lane * 4];
    float4 bb = *(const float4*)&be[lane * 4];
    float4 a2 = *(const float4*)&attn2[i];
    *(float4*)&outp[i] = make_float4(a2.x + dx*rs*gg.x + bb.x, a2.y + dy*rs*gg.y + bb.y,
                                     a2.z + dz*rs*gg.z + bb.z, a2.w + dw*rs*gg.w + bb.w);
}

// ---------------- adaptive avg pool over node axis -------------------------
__global__ void pool_kernel(const float* __restrict__ Kin, const float* __restrict__ Vin,
                            float* __restrict__ Kp, float* __restrict__ Vp)
{
    int bt = blockIdx.x, c = blockIdx.y, d = threadIdx.x;
    int s = (c * NNODE) / CC;
    int e = ((c + 1) * NNODE + CC - 1) / CC;
    float inv = 1.f / (float)(e - s);
    float ak = 0.f, av = 0.f;
    for (int n = s; n < e; n++) {
        ak += Kin[((size_t)bt * NNODE + n) * DD + d];
        av += Vin[((size_t)bt * NNODE + n) * DD + d];
    }
    Kp[((size_t)bt * CC + c) * DD + d] = ak * inv;
    Vp[((size_t)bt * CC + c) * DD + d] = av * inv;
}

// ---------------- dtw attention: 400 keys, block = (bt, head) --------------
__global__ __launch_bounds__(256) void attn_dtw_kernel(
    const float* __restrict__ Q, const float* __restrict__ K,
    const float* __restrict__ V, float* __restrict__ O)
{
    extern __shared__ float sm[];
    float* Qs = sm;               // 400*16
    float* Kt = sm + 6400;        // 16*416
    float* Vt = sm + 6400 + 6656;
    int bt = blockIdx.x, h = blockIdx.y;
    size_t base = ((size_t)bt * NNODE) * DD + h * HDIM;
    int tid = threadIdx.x;
    for (int e = tid; e < NNODE * 4; e += 256) {
        int q = e >> 2, d4 = (e & 3) << 2;
        float4 qv = *(const float4*)&Q[base + (size_t)q * DD + d4];
        float4 kv = *(const float4*)&K[base + (size_t)q * DD + d4];
        float4 vv = *(const float4*)&V[base + (size_t)q * DD + d4];
        *(float4*)&Qs[q * 16 + d4] = qv;
        Kt[(d4 + 0) * 416 + q] = kv.x; Kt[(d4 + 1) * 416 + q] = kv.y;
        Kt[(d4 + 2) * 416 + q] = kv.z; Kt[(d4 + 3) * 416 + q] = kv.w;
        Vt[(d4 + 0) * 416 + q] = vv.x; Vt[(d4 + 1) * 416 + q] = vv.y;
        Vt[(d4 + 2) * 416 + q] = vv.z; Vt[(d4 + 3) * 416 + q] = vv.w;
    }
    __syncthreads();
    int warp = tid >> 5, lane = tid & 31;
    for (int pp = warp; pp < NNODE / 2; pp += 8) {
        int qa = pp * 2;
        float qva[16], qvb[16];
#pragma unroll
        for (int d = 0; d < 16; d++) {
            qva[d] = Qs[qa * 16 + d];
            qvb[d] = Qs[qa * 16 + 16 + d];
        }
        float sa[13], sbv[13];
        float mxa = -1e30f, mxb = -1e30f;
#pragma unroll
        for (int i = 0; i < 13; i++) {
            int j = lane + (i << 5);
            float s0 = -1e30f, s1 = -1e30f;
            if (j < NNODE) {
                s0 = 0.f; s1 = 0.f;
#pragma unroll
                for (int d = 0; d < 16; d++) {
                    float kv = Kt[d * 416 + j];
                    s0 = fmaf(qva[d], kv, s0);
                    s1 = fmaf(qvb[d], kv, s1);
                }
                s0 *= 0.25f; s1 *= 0.25f;
            }
            sa[i] = s0; sbv[i] = s1;
            mxa = fmaxf(mxa, s0); mxb = fmaxf(mxb, s1);
        }
#pragma unroll
        for (int o = 16; o; o >>= 1) {
            mxa = fmaxf(mxa, __shfl_xor_sync(0xffffffffu, mxa, o));
            mxb = fmaxf(mxb, __shfl_xor_sync(0xffffffffu, mxb, o));
        }
        float la = 0.f, lb = 0.f;
#pragma unroll
        for (int i = 0; i < 13; i++) {
            int j = lane + (i << 5);
            float pa = (j < NNODE) ? __expf(sa[i] - mxa) : 0.f;
            float pb = (j < NNODE) ? __expf(sbv[i] - mxb) : 0.f;
            sa[i] = pa; sbv[i] = pb;
            la += pa; lb += pb;
        }
#pragma unroll
        for (int o = 16; o; o >>= 1) {
            la += __shfl_xor_sync(0xffffffffu, la, o);
            lb += __shfl_xor_sync(0xffffffffu, lb, o);
        }
        float acca[16], accb[16];
#pragma unroll
        for (int d = 0; d < 16; d++) { acca[d] = 0.f; accb[d] = 0.f; }
#pragma unroll
        for (int i = 0; i < 13; i++) {
            int j = lane + (i << 5);
            if (j < NNODE) {
                float pa = sa[i], pb = sbv[i];
#pragma unroll
                for (int d = 0; d < 16; d++) {
                    float vv = Vt[d * 416 + j];
                    acca[d] = fmaf(pa, vv, acca[d]);
                    accb[d] = fmaf(pb, vv, accb[d]);
                }
            }
        }
#pragma unroll
        for (int d = 0; d < 16; d++) {
#pragma unroll
            for (int o = 16; o; o >>= 1) {
                acca[d] += __shfl_xor_sync(0xffffffffu, acca[d], o);
                accb[d] += __shfl_xor_sync(0xffffffffu, accb[d], o);
            }
        }
        if (lane < 16) {
            O[base + (size_t)qa * DD + lane]       = acca[lane] / la;
            O[base + (size_t)(qa + 1) * DD + lane] = accb[lane] / lb;
        }
    }
}

// ---------------- pooled attention: 64 keys + positional bias --------------
__global__ __launch_bounds__(256) void attn_adp_kernel(
    const float* __restrict__ Q, const float* __restrict__ Kp,
    const float* __restrict__ Vp, const float* __restrict__ pos,
    float* __restrict__ O)
{
    __shared__ float Qs[NNODE * 16];
    __shared__ float Kt[16 * 64];
    __shared__ float Vt[16 * 64];
    int bt = blockIdx.x, h = blockIdx.y, tid = threadIdx.x;
    size_t qbase = ((size_t)bt * NNODE) * DD + h * HDIM;
    size_t kbase = ((size_t)bt * CC) * DD + h * HDIM;
    for (int e = tid; e < NNODE * 4; e += 256) {
        int q = e >> 2, d4 = (e & 3) << 2;
        *(float4*)&Qs[q * 16 + d4] = *(const float4*)&Q[qbase + (size_t)q * DD + d4];
    }
    {
        int c = tid >> 2, d4 = (tid & 3) << 2;
        float4 kv = *(const float4*)&Kp[kbase + (size_t)c * DD + d4];
        float4 vv = *(const float4*)&Vp[kbase + (size_t)c * DD + d4];
        Kt[(d4 + 0) * 64 + c] = kv.x; Kt[(d4 + 1) * 64 + c] = kv.y;
        Kt[(d4 + 2) * 64 + c] = kv.z; Kt[(d4 + 3) * 64 + c] = kv.w;
        Vt[(d4 + 0) * 64 + c] = vv.x; Vt[(d4 + 1) * 64 + c] = vv.y;
        Vt[(d4 + 2) * 64 + c] = vv.z; Vt[(d4 + 3) * 64 + c] = vv.w;
    }
    __syncthreads();
    int warp = tid >> 5, lane = tid & 31;
    for (int pp = warp; pp < NNODE / 2; pp += 8) {
        int qa = pp * 2;
        float qva[16], qvb[16];
#pragma unroll
        for (int d = 0; d < 16; d++) {
            qva[d] = Qs[qa * 16 + d];
            qvb[d] = Qs[qa * 16 + 16 + d];
        }
        float s00 = 0.f, s01 = 0.f, s10 = 0.f, s11 = 0.f;
#pragma unroll
        for (int d = 0; d < 16; d++) {
            float k0 = Kt[d * 64 + lane], k1 = Kt[d * 64 + lane + 32];
            s00 = fmaf(qva[d], k0, s00); s01 = fmaf(qva[d], k1, s01);
            s10 = fmaf(qvb[d], k0, s10); s11 = fmaf(qvb[d], k1, s11);
        }
        s00 = s00 * 0.25f + pos[(size_t)qa * 64 + lane];
        s01 = s01 * 0.25f + pos[(size_t)qa * 64 + lane + 32];
        s10 = s10 * 0.25f + pos[(size_t)(qa + 1) * 64 + lane];
        s11 = s11 * 0.25f + pos[(size_t)(qa + 1) * 64 + lane + 32];
        float mxa = fmaxf(s00, s01), mxb = fmaxf(s10, s11);
#pragma unroll
        for (int o = 16; o; o >>= 1) {
            mxa = fmaxf(mxa, __shfl_xor_sync(0xffffffffu, mxa, o));
            mxb = fmaxf(mxb, __shfl_xor_sync(0xffffffffu, mxb, o));
        }
        float p00 = __expf(s00 - mxa), p01 = __expf(s01 - mxa);
        float p10 = __expf(s10 - mxb), p11 = __expf(s11 - mxb);
        float la = p00 + p01, lb = p10 + p11;
#pragma unroll
        for (int o = 16; o; o >>= 1) {
            la += __shfl_xor_sync(0xffffffffu, la, o);
            lb += __shfl_xor_sync(0xffffffffu, lb, o);
        }
        float acca[16], accb[16];
#pragma unroll
        for (int d = 0; d < 16; d++) {
            float v0 = Vt[d * 64 + lane], v1 = Vt[d * 64 + lane + 32];
            acca[d] = p00 * v0 + p01 * v1;
            accb[d] = p10 * v0 + p11 * v1;
        }
#pragma unroll
        for (int d = 0; d < 16; d++) {
#pragma unroll
            for (int o = 16; o; o >>= 1) {
                acca[d] += __shfl_xor_sync(0xffffffffu, acca[d], o);
                accb[d] += __shfl_xor_sync(0xffffffffu, accb[d], o);
            }
        }
        if (lane < 16) {
            O[qbase + (size_t)qa * DD + lane]       = acca[lane] / la;
            O[qbase + (size_t)(qa + 1) * DD + lane] = accb[lane] / lb;
        }
    }
}

// ---------------- GEANet edge path (sen -> sen_extra) ----------------------
__global__ void edge_kernel(const float* __restrict__ elin, const float* __restrict__ ew,
                            const float* __restrict__ eb, float* __restrict__ senx,
                            float* __restrict__ outtail)
{
    __shared__ float s0[128], s1[128], s2[128];
    int n = blockIdx.x, t = threadIdx.x;
    int h = t >> 4, u = t & 15;
    s0[t] = elin[(size_t)n * 128 + t];
    __syncthreads();
    float acc = eb[u];
#pragma unroll
    for (int k = 0; k < 16; k++) acc = fmaf(s0[k * 8 + h], ew[k * 16 + u], acc);
    s1[t] = acc;
    __syncthreads();
    float mx = -1e30f;
#pragma unroll
    for (int hh = 0; hh < 8; hh++) mx = fmaxf(mx, s1[hh * 16 + u]);
    float sume = 0.f;
#pragma unroll
    for (int hh = 0; hh < 8; hh++) sume += __expf(s1[hh * 16 + u] - mx);
    float a = __expf(acc - mx) / sume;
    s2[t] = a;
    __syncthreads();
    float rs = 0.f;
#pragma unroll
    for (int uu = 0; uu < 16; uu++) rs += s2[h * 16 + uu];
    float a2 = a / rs;
    __syncthreads();
    s0[t] = a2;
    __syncthreads();
    float y = eb[16 + u];
#pragma unroll
    for (int k = 0; k < 16; k++) y = fmaf(s0[h * 16 + k], ew[256 + k * 16 + u], y);
    senx[(size_t)n * 128 + t] = y;
    outtail[(size_t)n * 128 + t] = y;
}

// ---------------- GEANet node path (reshape-of-transpose perm) -------------
__global__ void node_kernel(const float* __restrict__ share, const float* __restrict__ nw,
                            const float* __restrict__ nb, float* __restrict__ extra)
{
    __shared__ float s0[128], s1[128], s2[128];
    int row = blockIdx.x;
    int b = row / (TT * NNODE), p = row % (TT * NNODE);
    int nn = p / TT, ll = p % TT;
    int t = threadIdx.x;
    int h = t >> 4, u = t & 15;
    s0[t] = share[(((size_t)b * TT + ll) * NNODE + nn) * 128 + t];
    __syncthreads();
    float acc = nb[u];
#pragma unroll
    for (int k = 0; k < 16; k++) acc = fmaf(s0[h * 16 + k], nw[k * 16 + u], acc);
    s1[t] = acc;
    __syncthreads();
    float mx = -1e30f;
#pragma unroll
    for (int hh = 0; hh < 8; hh++) mx = fmaxf(mx, s1[hh * 16 + u]);
    float sume = 0.f;
#pragma unroll
    for (int hh = 0; hh < 8; hh++) sume += __expf(s1[hh * 16 + u] - mx);
    float a = __expf(acc - mx) / sume;
    s2[t] = a;
    __syncthreads();
    float rs = 0.f;
#pragma unroll
    for (int uu = 0; uu < 16; uu++) rs += s2[h * 16 + uu];
    float a2 = a / rs;
    __syncthreads();
    s0[t] = a2;
    __syncthreads();
    float y = nb[16 + u];
#pragma unroll
    for (int k = 0; k < 16; k++) y = fmaf(s0[h * 16 + k], nw[256 + k * 16 + u], y);
    extra[(size_t)row * 128 + t] = y;
}

// ---------------- host orchestration ---------------------------------------
extern "C" void kernel_launch(void* const* d_in, const int* in_sizes, int n_in,
                              void* d_out, int out_size)
{
    const float* x         = (const float*)d_in[0];
    const float* spe       = (const float*)d_in[1];
    const float* dtw_qkv_w = (const float*)d_in[2];
    const float* dtw_qkv_b = (const float*)d_in[3];
    const float* dtw_out_w = (const float*)d_in[4];
    const float* dtw_out_b = (const float*)d_in[5];
    const float* att_qkv_w = (const float*)d_in[6];
    const float* att_qkv_b = (const float*)d_in[7];
    const float* att_out_w = (const float*)d_in[8];
    const float* att_out_b = (const float*)d_in[9];
    const float* adp_pos   = (const float*)d_in[10];
    const float* share_w   = (const float*)d_in[11];
    const float* share_b   = (const float*)d_in[12];
    const float* node_w    = (const float*)d_in[13];
    const float* node_b    = (const float*)d_in[14];
    const float* edge_w    = (const float*)d_in[15];
    const float* edge_b    = (const float*)d_in[16];
    const float* spatial_w = (const float*)d_in[17];
    const float* spatial_b = (const float*)d_in[18];
    const float* ff1w1     = (const float*)d_in[19];
    const float* ff1b1     = (const float*)d_in[20];
    const float* ff1w2     = (const float*)d_in[21];
    const float* ff1b2     = (const float*)d_in[22];
    const float* ff2w1     = (const float*)d_in[23];
    const float* ff2b1     = (const float*)d_in[24];
    const float* ff2w2     = (const float*)d_in[25];
    const float* ff2b2     = (const float*)d_in[26];
    const float* lns       = (const float*)d_in[27];
    const float* lnb       = (const float*)d_in[28];
    float* out = (float*)d_out;

    float* g = nullptr;
    { void* p; cudaGetSymbolAddress(&p, g_scratch); g = (float*)p; }
    float* PART = g + 0u * CHSZ;           // 4 split-K partials (chunks 0-3)
    float* Q1   = g + 0u * CHSZ;
    float* K1   = g + 1u * CHSZ;
    float* V1   = g + 2u * CHSZ;
    float* Q2   = g + 3u * CHSZ;
    float* K2   = g + 4u * CHSZ;
    float* V2   = g + 5u * CHSZ;
    float* SHR  = g + 6u * CHSZ;
    float* DTW  = g + 7u * CHSZ;
    float* OA   = g + 8u * CHSZ;
    float* B1   = g + 9u * CHSZ;
    float* B2   = g + 10u * CHSZ;
    float* B3   = g + 11u * CHSZ;
    float* B4   = g + 12u * CHSZ;
    float* HID  = g + OFF_HID;
    float* KP   = g + OFF_KP;
    float* VP   = g + OFF_VP;
    float* SEN  = g + OFF_SEN;
    float* ELIN = g + OFF_ELIN;
    float* SENX = g + OFF_SENX;
    float* T400 = g + OFF_T400;

    cudaFuncSetAttribute(attn_dtw_kernel,
                         cudaFuncAttributeMaxDynamicSharedMemorySize, 78848);
    cudaFuncSetAttribute(gemm_tf32_kernel,
                         cudaFuncAttributeMaxDynamicSharedMemorySize, GEMM_SMEM);
    cudaFuncSetAttribute(gemm_multi_kernel,
                         cudaFuncAttributeMaxDynamicSharedMemorySize, GEMM_SMEM);

#define GEMM(A_, W_, Bi_, C_, M_, N_, K_, LDA_, R_) \
    gemm_tf32_kernel<<<dim3(((M_) + 127) / 128, (N_) / 128, 1), 256, GEMM_SMEM>>>( \
        A_, W_, Bi_, C_, M_, N_, K_, LDA_, 0, R_)

    // fused QKV projections + GEANet share (one launch, R8 core)
    {
        MultiArgs ma;
        ma.W[0] = dtw_qkv_w + 0 * DD * DD; ma.Bv[0] = dtw_qkv_b + 0 * DD; ma.C[0] = Q1;
        ma.W[1] = dtw_qkv_w + 1 * DD * DD; ma.Bv[1] = dtw_qkv_b + 1 * DD; ma.C[1] = K1;
        ma.W[2] = dtw_qkv_w + 2 * DD * DD; ma.Bv[2] = dtw_qkv_b + 2 * DD; ma.C[2] = V1;
        ma.W[3] = att_qkv_w + 0 * DD * DD; ma.Bv[3] = att_qkv_b + 0 * DD; ma.C[3] = Q2;
        ma.W[4] = att_qkv_w + 1 * DD * DD; ma.Bv[4] = att_qkv_b + 1 * DD; ma.C[4] = K2;
        ma.W[5] = att_qkv_w + 2 * DD * DD; ma.Bv[5] = att_qkv_b + 2 * DD; ma.C[5] = V2;
        ma.W[6] = share_w;                 ma.Bv[6] = share_b;            ma.C[6] = SHR;
        gemm_multi_kernel<<<dim3(MROWS / 128, 7), 256, GEMM_SMEM>>>(x, ma, MROWS);
    }

    // sen path
    GEMM(spe, spatial_w, spatial_b, T400, NNODE, DD, DD, DD, 0);
    ln_kernel<<<NNODE / 8, 256>>>(T400, lns + 3 * 128, lnb + 3 * 128, SEN);
    GEMM(SEN, share_w, share_b, ELIN, NNODE, DD, DD, DD, 0);
    edge_kernel<<<NNODE, 128>>>(ELIN, edge_w, edge_b, SENX, out + (size_t)MROWS * DD);

    // GEANet node path
    node_kernel<<<MROWS, 128>>>(SHR, node_w, node_b, B1);

    // dtw attention + out projection
    attn_dtw_kernel<<<dim3(BTN, HH), 256, 78848>>>(Q1, K1, V1, B2);
    GEMM(B2, dtw_out_w, dtw_out_b, DTW, MROWS, DD, DD, DD, 0);

    // pooled attention + out projection
    pool_kernel<<<dim3(BTN, CC), 128>>>(K2, V2, KP, VP);
    attn_adp_kernel<<<dim3(BTN, HH), 256>>>(Q2, KP, VP, adp_pos, B2);
    GEMM(B2, att_out_w, att_out_b, OA, MROWS, DD, DD, DD, 0);

    // ln1 of (x + oa + dtw + extra)
    lnsum4_kernel<<<MROWS / 8, 256>>>(x, OA, DTW, B1, lns + 0, lnb + 0, B4);

    // feed_forward1: up (relu) + split-K=4 down -> 4 partials; ln2 + senx mul
    GEMM(B4, ff1w1, ff1b1, HID, MROWS, FFD, DD, DD, 1);
    gemm_tf32_kernel<<<dim3(MROWS / 128, 1, 4), 256, GEMM_SMEM>>>(
        HID, ff1w2, ff1b2, PART, MROWS, DD, FFD / 4, FFD, (size_t)CHSZ, 0);
    ln2mul_kernel<<<MROWS / 8, 256>>>(PART, B4, SENX, lns + 128, lnb + 128, B2, B3);

    // feed_forward2: up (relu) + split-K=4 down; spatial_norm + residual
    GEMM(B3, ff2w1, ff2b1, HID, MROWS, FFD, DD, DD, 1);
    gemm_tf32_kernel<<<dim3(MROWS / 128, 1, 4), 256, GEMM_SMEM>>>(
        HID, ff2w2, ff2b2, PART, MROWS, DD, FFD / 4, FFD, (size_t)CHSZ, 0);
    final_kernel<<<MROWS / 8, 256>>>(PART, B2, lns + 2 * 128, lnb + 2 * 128, out);
#undef GEMM
}